// round 1
// baseline (speedup 1.0000x reference)
#include <cuda_runtime.h>

static constexpr int   kN  = 50000;
static constexpr int   kE  = 600000;
static constexpr int   kC  = 128;
static constexpr int   kG  = 256;
static constexpr float kPI = 3.14159265358979323846f;

// ---------------- scratch (device globals; no allocation allowed) ----------------
__device__ int   g_deg[kN];
__device__ int   g_rowptr[kN + 1];
__device__ int   g_fill[kN];
__device__ int   g_csr_src[kE];
__device__ int   g_csr_eid[kE];
__device__ int   g_bsums[512];
__device__ int   g_gcnt[kG];
__device__ int   g_gptr[kG + 1];
__device__ float g_loop[kN * kC];
__device__ float g_xl[kN * kC];
__device__ float g_xr[kN * kC];
__device__ float g_h[kN * kC];
__device__ float g_ase[kE];
__device__ float g_asf[kN];
__device__ float g_bns[2 * kC];
__device__ float g_p[kG * kC];

// ---------------- small utility kernels ----------------
__global__ void zero_i(int* p, int n) {
    int i = blockIdx.x * blockDim.x + threadIdx.x;
    if (i < n) p[i] = 0;
}
__global__ void zero_f(float* p, int n) {
    int i = blockIdx.x * blockDim.x + threadIdx.x;
    if (i < n) p[i] = 0.f;
}
__global__ void hist_kernel(const int* __restrict__ keys, int* __restrict__ cnt, int n) {
    int i = blockIdx.x * blockDim.x + threadIdx.x;
    if (i < n) atomicAdd(&cnt[keys[i]], 1);
}

// exclusive scan: pass 1 (per-block)
__global__ void scan_block(const int* __restrict__ in, int* __restrict__ out,
                           int* __restrict__ bsums, int n) {
    __shared__ int sm[512];
    int tid = threadIdx.x;
    int i = blockIdx.x * 512 + tid;
    int v = (i < n) ? in[i] : 0;
    sm[tid] = v;
    __syncthreads();
#pragma unroll
    for (int off = 1; off < 512; off <<= 1) {
        int t = (tid >= off) ? sm[tid - off] : 0;
        __syncthreads();
        sm[tid] += t;
        __syncthreads();
    }
    if (i < n) out[i] = sm[tid] - v;           // exclusive within block
    if (tid == 511) bsums[blockIdx.x] = sm[511];
}
// pass 2: exclusive scan of block sums (single block)
__global__ void scan_sums(int* bsums, int nb) {
    __shared__ int sm[512];
    int tid = threadIdx.x;
    int v = (tid < nb) ? bsums[tid] : 0;
    sm[tid] = v;
    __syncthreads();
#pragma unroll
    for (int off = 1; off < 512; off <<= 1) {
        int t = (tid >= off) ? sm[tid - off] : 0;
        __syncthreads();
        sm[tid] += t;
        __syncthreads();
    }
    if (tid < nb) bsums[tid] = sm[tid] - v;    // exclusive
}
// pass 3: add block offsets; write tail (rowptr[N] = E)
__global__ void scan_add(int* out, const int* __restrict__ bsums, int n, int total, int* tail) {
    int i = blockIdx.x * 512 + threadIdx.x;
    if (i < n) out[i] += bsums[blockIdx.x];
    if (blockIdx.x == 0 && threadIdx.x == 0) *tail = total;
}
// graph-pointer scan (G=256 fits one block)
__global__ void gscan(const int* __restrict__ cnt, int* __restrict__ gptr) {
    __shared__ int sm[256];
    int t = threadIdx.x;
    sm[t] = cnt[t];
    __syncthreads();
#pragma unroll
    for (int off = 1; off < 256; off <<= 1) {
        int u = (t >= off) ? sm[t - off] : 0;
        __syncthreads();
        sm[t] += u;
        __syncthreads();
    }
    if (t == 0) gptr[0] = 0;
    gptr[t + 1] = sm[t];                        // inclusive -> start of next
}
__global__ void scatter_kernel(const int* __restrict__ src, const int* __restrict__ dst,
                               const int* __restrict__ rowptr, int* __restrict__ fill,
                               int* __restrict__ csr_src, int* __restrict__ csr_eid, int n) {
    int i = blockIdx.x * blockDim.x + threadIdx.x;
    if (i >= n) return;
    int d = dst[i];
    int pos = rowptr[d] + atomicAdd(&fill[d], 1);
    csr_src[pos] = src[i];
    csr_eid[pos] = i;
}

// loop_attr[n] = mean of incoming edge_attr (warp per node)
__global__ void __launch_bounds__(256) loopattr_kernel(const float* __restrict__ ea,
                                                       const int* __restrict__ rowptr,
                                                       const int* __restrict__ csr_eid,
                                                       float* __restrict__ loopb) {
    int w = (blockIdx.x * blockDim.x + threadIdx.x) >> 5;
    int lane = threadIdx.x & 31;
    if (w >= kN) return;
    int b0 = rowptr[w], b1 = rowptr[w + 1];
    float4 acc = make_float4(0.f, 0.f, 0.f, 0.f);
    const float4* ea4 = (const float4*)ea;
    for (int j = b0; j < b1; j++) {
        float4 v = ea4[(size_t)csr_eid[j] * 32 + lane];
        acc.x += v.x; acc.y += v.y; acc.z += v.z; acc.w += v.w;
    }
    int dg = b1 - b0;
    float inv = 1.f / (float)(dg > 0 ? dg : 1);
    acc.x *= inv; acc.y *= inv; acc.z *= inv; acc.w *= inv;
    ((float4*)loopb)[(size_t)w * 32 + lane] = acc;
}

// ---------------- generic node GEMM: out[M,128] = A[M,128] @ B[128,128] + bias ----------------
template <int ACT>   // 0 = none, 1 = tanh
__global__ void __launch_bounds__(256) gemm_node(const float* __restrict__ A,
                                                 const float* __restrict__ B,
                                                 const float* __restrict__ bias,
                                                 float* __restrict__ out, int M) {
    __shared__ float As[16][136];
    __shared__ float Bs[16][128];
    const int tid = threadIdx.x;
    const int tx = tid & 15, ty = tid >> 4;
    const int row0 = blockIdx.x * 128;
    float acc[8][8];
#pragma unroll
    for (int i = 0; i < 8; i++)
#pragma unroll
        for (int j = 0; j < 8; j++) acc[i][j] = 0.f;

    for (int k0 = 0; k0 < 128; k0 += 16) {
#pragma unroll
        for (int hh = 0; hh < 2; hh++) {
            int idx = tid + hh * 256;
            int r = idx >> 2;
            int kk = (idx & 3) << 2;
            int grow = row0 + r;
            float4 av = make_float4(0.f, 0.f, 0.f, 0.f);
            if (grow < M) av = *(const float4*)(A + (size_t)grow * 128 + k0 + kk);
            As[kk + 0][r] = av.x; As[kk + 1][r] = av.y;
            As[kk + 2][r] = av.z; As[kk + 3][r] = av.w;
            int rb = idx >> 5;
            int cb = (idx & 31) << 2;
            *(float4*)(&Bs[rb][cb]) = *(const float4*)(B + (size_t)(k0 + rb) * 128 + cb);
        }
        __syncthreads();
#pragma unroll
        for (int kk = 0; kk < 16; kk++) {
            float a[8], b[8];
            float4 va0 = *(const float4*)(&As[kk][ty * 8]);
            float4 va1 = *(const float4*)(&As[kk][ty * 8 + 4]);
            float4 vb0 = *(const float4*)(&Bs[kk][tx * 8]);
            float4 vb1 = *(const float4*)(&Bs[kk][tx * 8 + 4]);
            a[0] = va0.x; a[1] = va0.y; a[2] = va0.z; a[3] = va0.w;
            a[4] = va1.x; a[5] = va1.y; a[6] = va1.z; a[7] = va1.w;
            b[0] = vb0.x; b[1] = vb0.y; b[2] = vb0.z; b[3] = vb0.w;
            b[4] = vb1.x; b[5] = vb1.y; b[6] = vb1.z; b[7] = vb1.w;
#pragma unroll
            for (int i = 0; i < 8; i++)
#pragma unroll
                for (int j = 0; j < 8; j++) acc[i][j] = fmaf(a[i], b[j], acc[i][j]);
        }
        __syncthreads();
    }
#pragma unroll
    for (int i = 0; i < 8; i++) {
        int r = row0 + ty * 8 + i;
        if (r < M) {
#pragma unroll
            for (int j = 0; j < 8; j++) {
                int c = tx * 8 + j;
                float v = acc[i][j] + bias[c];
                if (ACT == 1) v = tanhf(v);
                out[(size_t)r * 128 + c] = v;
            }
        }
    }
}

// ---------------- fused attention-score GEMM ----------------
// a[r] = sum_c leaky( (A@We)[r,c] + xl[s_r,c] + xr[d_r,c] ) * att[c]
// SELF: s_r = d_r = r (self-loop scores over loop_attr rows)
template <bool SELF>
__global__ void __launch_bounds__(256) gemm_score(const float* __restrict__ A,
                                                  const float* __restrict__ B,
                                                  const float* __restrict__ att,
                                                  const float* __restrict__ xl,
                                                  const float* __restrict__ xr,
                                                  const int* __restrict__ src,
                                                  const int* __restrict__ dst,
                                                  float* __restrict__ aout, int M) {
    __shared__ float As[16][136];
    __shared__ float Bs[16][128];
    __shared__ int   sS[128];
    __shared__ int   sD[128];
    __shared__ float attS[128];
    const int tid = threadIdx.x;
    const int tx = tid & 15, ty = tid >> 4;
    const int row0 = blockIdx.x * 128;

    if (tid < 128) {
        int r = row0 + tid;
        int rc = (r < M) ? r : (M - 1);
        sS[tid] = SELF ? rc : src[rc];
        sD[tid] = SELF ? rc : dst[rc];
        attS[tid] = att[tid];
    }

    float acc[8][8];
#pragma unroll
    for (int i = 0; i < 8; i++)
#pragma unroll
        for (int j = 0; j < 8; j++) acc[i][j] = 0.f;

    for (int k0 = 0; k0 < 128; k0 += 16) {
#pragma unroll
        for (int hh = 0; hh < 2; hh++) {
            int idx = tid + hh * 256;
            int r = idx >> 2;
            int kk = (idx & 3) << 2;
            int grow = row0 + r;
            float4 av = make_float4(0.f, 0.f, 0.f, 0.f);
            if (grow < M) av = *(const float4*)(A + (size_t)grow * 128 + k0 + kk);
            As[kk + 0][r] = av.x; As[kk + 1][r] = av.y;
            As[kk + 2][r] = av.z; As[kk + 3][r] = av.w;
            int rb = idx >> 5;
            int cb = (idx & 31) << 2;
            *(float4*)(&Bs[rb][cb]) = *(const float4*)(B + (size_t)(k0 + rb) * 128 + cb);
        }
        __syncthreads();
#pragma unroll
        for (int kk = 0; kk < 16; kk++) {
            float a[8], b[8];
            float4 va0 = *(const float4*)(&As[kk][ty * 8]);
            float4 va1 = *(const float4*)(&As[kk][ty * 8 + 4]);
            float4 vb0 = *(const float4*)(&Bs[kk][tx * 8]);
            float4 vb1 = *(const float4*)(&Bs[kk][tx * 8 + 4]);
            a[0] = va0.x; a[1] = va0.y; a[2] = va0.z; a[3] = va0.w;
            a[4] = va1.x; a[5] = va1.y; a[6] = va1.z; a[7] = va1.w;
            b[0] = vb0.x; b[1] = vb0.y; b[2] = vb0.z; b[3] = vb0.w;
            b[4] = vb1.x; b[5] = vb1.y; b[6] = vb1.z; b[7] = vb1.w;
#pragma unroll
            for (int i = 0; i < 8; i++)
#pragma unroll
                for (int j = 0; j < 8; j++) acc[i][j] = fmaf(a[i], b[j], acc[i][j]);
        }
        __syncthreads();
    }
    // epilogue: gather xl[s], xr[d], leaky, dot with att, reduce across 16 col-threads
#pragma unroll
    for (int i = 0; i < 8; i++) {
        int er = ty * 8 + i;
        int s = sS[er], d = sD[er];
        const float4* xlp = (const float4*)(xl + (size_t)s * 128 + tx * 8);
        const float4* xrp = (const float4*)(xr + (size_t)d * 128 + tx * 8);
        float4 xa0 = xlp[0], xa1 = xlp[1];
        float4 xb0 = xrp[0], xb1 = xrp[1];
        float xlv[8] = {xa0.x, xa0.y, xa0.z, xa0.w, xa1.x, xa1.y, xa1.z, xa1.w};
        float xrv[8] = {xb0.x, xb0.y, xb0.z, xb0.w, xb1.x, xb1.y, xb1.z, xb1.w};
        float pa = 0.f;
#pragma unroll
        for (int j = 0; j < 8; j++) {
            float v = acc[i][j] + xlv[j] + xrv[j];
            v = (v > 0.f) ? v : 0.2f * v;
            pa = fmaf(v, attS[tx * 8 + j], pa);
        }
#pragma unroll
        for (int off = 8; off; off >>= 1) pa += __shfl_xor_sync(0xffffffffu, pa, off);
        if (tx == 0) {
            int r = row0 + er;
            if (r < M) aout[r] = pa;
        }
    }
}

// ---------------- softmax + aggregation (warp per node, CSR) ----------------
__global__ void __launch_bounds__(256) aggregate_kernel(const int* __restrict__ rowptr,
                                                        const int* __restrict__ csr_src,
                                                        const int* __restrict__ csr_eid,
                                                        const float* __restrict__ ae,
                                                        const float* __restrict__ as,
                                                        const float* __restrict__ xl,
                                                        const float* __restrict__ bo,
                                                        float* __restrict__ h) {
    int n = (blockIdx.x * blockDim.x + threadIdx.x) >> 5;
    int lane = threadIdx.x & 31;
    if (n >= kN) return;
    int b0 = rowptr[n], b1 = rowptr[n + 1];
    float aself = as[n];
    float am = aself;
    for (int j = b0 + lane; j < b1; j += 32) am = fmaxf(am, ae[csr_eid[j]]);
#pragma unroll
    for (int off = 16; off; off >>= 1) am = fmaxf(am, __shfl_xor_sync(0xffffffffu, am, off));
    float den = 0.f;
    for (int j = b0 + lane; j < b1; j += 32) den += __expf(ae[csr_eid[j]] - am);
#pragma unroll
    for (int off = 16; off; off >>= 1) den += __shfl_xor_sync(0xffffffffu, den, off);
    float wself = __expf(aself - am);
    den += wself;
    float inv = 1.f / den;

    float4 acc = make_float4(0.f, 0.f, 0.f, 0.f);
    const float4* xl4 = (const float4*)xl;
    for (int j = b0; j < b1; j++) {
        float w = __expf(ae[csr_eid[j]] - am) * inv;
        float4 v = xl4[(size_t)csr_src[j] * 32 + lane];
        acc.x = fmaf(w, v.x, acc.x); acc.y = fmaf(w, v.y, acc.y);
        acc.z = fmaf(w, v.z, acc.z); acc.w = fmaf(w, v.w, acc.w);
    }
    {
        float w = wself * inv;
        float4 v = xl4[(size_t)n * 32 + lane];
        acc.x = fmaf(w, v.x, acc.x); acc.y = fmaf(w, v.y, acc.y);
        acc.z = fmaf(w, v.z, acc.z); acc.w = fmaf(w, v.w, acc.w);
    }
    float4 b = ((const float4*)bo)[lane];
    acc.x += b.x; acc.y += b.y; acc.z += b.z; acc.w += b.w;
    ((float4*)h)[(size_t)n * 32 + lane] = acc;
}

// ---------------- batchnorm ----------------
__global__ void bn_stats(const float* __restrict__ h, float* __restrict__ st) {
    int c = threadIdx.x;   // 128 threads
    float s = 0.f, s2 = 0.f;
    for (int r = blockIdx.x; r < kN; r += gridDim.x) {
        float v = h[(size_t)r * 128 + c];
        s += v;
        s2 = fmaf(v, v, s2);
    }
    atomicAdd(&st[c], s);
    atomicAdd(&st[128 + c], s2);
}
__global__ void bn_apply(float* __restrict__ h, const float* __restrict__ st,
                         const float* __restrict__ g, const float* __restrict__ b) {
    int c = threadIdx.x;
    float mean = st[c] * (1.f / (float)kN);
    float var = st[128 + c] * (1.f / (float)kN) - mean * mean;
    float sc = rsqrtf(var + 1e-5f) * g[c];
    float sh = b[c] - mean * sc;
    for (int r = blockIdx.x; r < kN; r += gridDim.x) {
        float v = h[(size_t)r * 128 + c];
        h[(size_t)r * 128 + c] = tanhf(fmaf(v, sc, sh));
    }
}

// ---------------- attentional pooling (block per graph) ----------------
__global__ void pool_kernel(const float* __restrict__ gate, const float* __restrict__ h,
                            const int* __restrict__ gptr, float* __restrict__ p) {
    int g = blockIdx.x, c = threadIdx.x;
    int s0 = gptr[g], s1 = gptr[g + 1];
    if (s0 == s1) { p[(size_t)g * 128 + c] = 0.f; return; }
    float m = -1e30f;
    for (int n = s0; n < s1; n++) m = fmaxf(m, gate[(size_t)n * 128 + c]);
    float den = 0.f, acc = 0.f;
    for (int n = s0; n < s1; n++) {
        float e = __expf(gate[(size_t)n * 128 + c] - m);
        den += e;
        acc = fmaf(e, h[(size_t)n * 128 + c], acc);
    }
    p[(size_t)g * 128 + c] = acc / den;
}

// ---------------- final linear + tanh + output split/scale ----------------
__global__ void final_kernel(const float* __restrict__ p, const float* __restrict__ Wf,
                             const float* __restrict__ bf, float* __restrict__ out) {
    int g = blockIdx.x, c = threadIdx.x;
    __shared__ float ps[128];
    ps[c] = p[(size_t)g * 128 + c];
    __syncthreads();
    float acc = bf[c];
#pragma unroll 8
    for (int k = 0; k < 128; k++) acc = fmaf(ps[k], Wf[(size_t)k * 128 + c], acc);
    float o = tanhf(acc);
    if (c < 64) out[(size_t)g * 64 + c] = o * kPI;
    else        out[(size_t)kG * 64 + (size_t)g * 64 + (c - 64)] = (o + 1.f) * kPI;
}

// ---------------- launch ----------------
extern "C" void kernel_launch(void* const* d_in, const int* in_sizes, int n_in,
                              void* d_out, int out_size) {
    (void)in_sizes; (void)n_in; (void)out_size;
    const float* x    = (const float*)d_in[0];
    const int*   ei   = (const int*)  d_in[1];
    const float* ea   = (const float*)d_in[2];
    const int*   bat  = (const int*)  d_in[3];
    const float* Wl1  = (const float*)d_in[4];
    const float* bl1  = (const float*)d_in[5];
    const float* Wr1  = (const float*)d_in[6];
    const float* br1  = (const float*)d_in[7];
    const float* We1  = (const float*)d_in[8];
    const float* att1 = (const float*)d_in[9];
    const float* bo1  = (const float*)d_in[10];
    const float* Wl2  = (const float*)d_in[11];
    const float* bl2  = (const float*)d_in[12];
    const float* Wr2  = (const float*)d_in[13];
    const float* br2  = (const float*)d_in[14];
    const float* We2  = (const float*)d_in[15];
    const float* att2 = (const float*)d_in[16];
    const float* bo2  = (const float*)d_in[17];
    const float* g1   = (const float*)d_in[18];
    const float* be1  = (const float*)d_in[19];
    const float* g2   = (const float*)d_in[20];
    const float* be2  = (const float*)d_in[21];
    const float* Ag1  = (const float*)d_in[22];
    const float* bg1  = (const float*)d_in[23];
    const float* Ag2  = (const float*)d_in[24];
    const float* bg2  = (const float*)d_in[25];
    const float* Wf   = (const float*)d_in[26];
    const float* bf   = (const float*)d_in[27];
    float* out = (float*)d_out;

    int *deg, *rowptr, *fill, *csr_src, *csr_eid, *bsums, *gcnt, *gptr;
    float *loopb, *xl, *xr, *h, *ase, *asf, *bns, *pbuf;
    cudaGetSymbolAddress((void**)&deg,     g_deg);
    cudaGetSymbolAddress((void**)&rowptr,  g_rowptr);
    cudaGetSymbolAddress((void**)&fill,    g_fill);
    cudaGetSymbolAddress((void**)&csr_src, g_csr_src);
    cudaGetSymbolAddress((void**)&csr_eid, g_csr_eid);
    cudaGetSymbolAddress((void**)&bsums,   g_bsums);
    cudaGetSymbolAddress((void**)&gcnt,    g_gcnt);
    cudaGetSymbolAddress((void**)&gptr,    g_gptr);
    cudaGetSymbolAddress((void**)&loopb,   g_loop);
    cudaGetSymbolAddress((void**)&xl,      g_xl);
    cudaGetSymbolAddress((void**)&xr,      g_xr);
    cudaGetSymbolAddress((void**)&h,       g_h);
    cudaGetSymbolAddress((void**)&ase,     g_ase);
    cudaGetSymbolAddress((void**)&asf,     g_asf);
    cudaGetSymbolAddress((void**)&bns,     g_bns);
    cudaGetSymbolAddress((void**)&pbuf,    g_p);

    const int* srcp = ei;
    const int* dstp = ei + kE;

    // ---- CSR + graph segmentation + loop_attr (layer-independent) ----
    zero_i<<<(kN + 255) / 256, 256>>>(deg, kN);
    zero_i<<<(kN + 255) / 256, 256>>>(fill, kN);
    zero_i<<<1, 256>>>(gcnt, kG);
    hist_kernel<<<(kE + 255) / 256, 256>>>(dstp, deg, kE);
    hist_kernel<<<(kN + 255) / 256, 256>>>(bat, gcnt, kN);
    const int nb = (kN + 511) / 512;
    scan_block<<<nb, 512>>>(deg, rowptr, bsums, kN);
    scan_sums<<<1, 512>>>(bsums, nb);
    scan_add<<<nb, 512>>>(rowptr, bsums, kN, kE, rowptr + kN);
    gscan<<<1, 256>>>(gcnt, gptr);
    scatter_kernel<<<(kE + 255) / 256, 256>>>(srcp, dstp, rowptr, fill, csr_src, csr_eid, kE);
    loopattr_kernel<<<(kN + 7) / 8, 256>>>(ea, rowptr, csr_eid, loopb);

    const int gN = (kN + 127) / 128;
    const int gE = (kE + 127) / 128;

    // ---- layer 1 ----
    gemm_node<0><<<gN, 256>>>(x, Wl1, bl1, xl, kN);
    gemm_node<0><<<gN, 256>>>(x, Wr1, br1, xr, kN);
    gemm_score<true><<<gN, 256>>>(loopb, We1, att1, xl, xr, (const int*)nullptr, (const int*)nullptr, asf, kN);
    gemm_score<false><<<gE, 256>>>(ea, We1, att1, xl, xr, srcp, dstp, ase, kE);
    aggregate_kernel<<<(kN + 7) / 8, 256>>>(rowptr, csr_src, csr_eid, ase, asf, xl, bo1, h);
    zero_f<<<1, 256>>>(bns, 2 * kC);
    bn_stats<<<512, 128>>>(h, bns);
    bn_apply<<<512, 128>>>(h, bns, g1, be1);

    // ---- layer 2 ----
    gemm_node<0><<<gN, 256>>>(h, Wl2, bl2, xl, kN);
    gemm_node<0><<<gN, 256>>>(h, Wr2, br2, xr, kN);
    gemm_score<true><<<gN, 256>>>(loopb, We2, att2, xl, xr, (const int*)nullptr, (const int*)nullptr, asf, kN);
    gemm_score<false><<<gE, 256>>>(ea, We2, att2, xl, xr, srcp, dstp, ase, kE);
    aggregate_kernel<<<(kN + 7) / 8, 256>>>(rowptr, csr_src, csr_eid, ase, asf, xl, bo2, h);
    zero_f<<<1, 256>>>(bns, 2 * kC);
    bn_stats<<<512, 128>>>(h, bns);
    bn_apply<<<512, 128>>>(h, bns, g2, be2);

    // ---- attentional pooling + final ----
    gemm_node<1><<<gN, 256>>>(h, Ag1, bg1, xl, kN);         // tanh(h@Ag1+bg1)
    gemm_node<0><<<gN, 256>>>(xl, Ag2, bg2, xr, kN);        // gate
    pool_kernel<<<kG, 128>>>(xr, h, gptr, pbuf);
    final_kernel<<<kG, 128>>>(pbuf, Wf, bf, out);
}